// round 13
// baseline (speedup 1.0000x reference)
#include <cuda_runtime.h>
#include <cuda_bf16.h>
#include <mma.h>
#include <cstdint>

using namespace nvcuda;

#define T_DIM   2048
#define B_DIM   128
#define IN_DIM  64
#define H_DIM   128
#define G_DIM   512
#define OUT_DIM 32
#define M_TOT   (T_DIM * B_DIM)   // 262144

typedef unsigned long long ull;

// scratch (device globals: allocation-free per harness rules)
__device__ __align__(16) float g_xp[(size_t)M_TOT * G_DIM];
__device__ __align__(16) float g_y [(size_t)M_TOT * H_DIM];
__device__ __align__(16) __nv_bfloat16 g_ah[(size_t)M_TOT * H_DIM];
__device__ __align__(16) __nv_bfloat16 g_al[(size_t)M_TOT * H_DIM];
__device__ __align__(16) __nv_bfloat16 g_wh[G_DIM * H_DIM];
__device__ __align__(16) __nv_bfloat16 g_wl[G_DIM * H_DIM];

// ---------------- activations ------------------------------------------------
__device__ __forceinline__ float tanh_f(float x) {
    float y; asm("tanh.approx.f32 %0, %1;" : "=f"(y) : "f"(x)); return y;
}
__device__ __forceinline__ float sigmoid_f(float x) {
    return 0.5f * tanh_f(0.5f * x) + 0.5f;
}
__device__ __forceinline__ ull fma2(ull a, ull b, ull c) {
    ull d; asm("fma.rn.f32x2 %0, %1, %2, %3;" : "=l"(d) : "l"(a), "l"(b), "l"(c));
    return d;
}
__device__ __forceinline__ float lo32(ull v) { return __uint_as_float((unsigned)(v & 0xffffffffu)); }
__device__ __forceinline__ float hi32(ull v) { return __uint_as_float((unsigned)(v >> 32)); }

// ---------------- fp32 -> bf16 hi/lo split -----------------------------------
__global__ void __launch_bounds__(256) conv_hl(const float* __restrict__ src,
                                               __nv_bfloat16* __restrict__ dh,
                                               __nv_bfloat16* __restrict__ dl,
                                               int n4)
{
    int i = blockIdx.x * 256 + threadIdx.x;
    if (i >= n4) return;
    float4 v = reinterpret_cast<const float4*>(src)[i];
    __nv_bfloat162 h0, h1, l0, l1;
    h0.x = __float2bfloat16_rn(v.x); h0.y = __float2bfloat16_rn(v.y);
    h1.x = __float2bfloat16_rn(v.z); h1.y = __float2bfloat16_rn(v.w);
    l0.x = __float2bfloat16_rn(v.x - __bfloat162float(h0.x));
    l0.y = __float2bfloat16_rn(v.y - __bfloat162float(h0.y));
    l1.x = __float2bfloat16_rn(v.z - __bfloat162float(h1.x));
    l1.y = __float2bfloat16_rn(v.w - __bfloat162float(h1.y));
    union { __nv_bfloat162 b[2]; uint2 u2; } ph, pl;
    ph.b[0] = h0; ph.b[1] = h1; pl.b[0] = l0; pl.b[1] = l1;
    reinterpret_cast<uint2*>(dh)[i] = ph.u2;
    reinterpret_cast<uint2*>(dl)[i] = pl.u2;
}

// ---------------- bf16(hi+lo) tensor-core GEMM with A-tile reuse (R12) -------
template<int K>
__global__ void __launch_bounds__(256) gemm_bf(const __nv_bfloat16* __restrict__ Ah,
                                               const __nv_bfloat16* __restrict__ Al,
                                               const __nv_bfloat16* __restrict__ Wh,
                                               const __nv_bfloat16* __restrict__ Wl,
                                               float* __restrict__ C)
{
    constexpr int LD  = K + 8;
    constexpr int V8  = K / 8;
    extern __shared__ __nv_bfloat16 sb[];
    __nv_bfloat16* Ahs = sb;                  // [128][LD]
    __nv_bfloat16* Als = Ahs + 128 * LD;
    __nv_bfloat16* Whs = Als + 128 * LD;      // [64][LD]
    __nv_bfloat16* Wls = Whs + 64 * LD;

    const int tid = threadIdx.x;
    const int m0 = blockIdx.y * 128;
    const int nb = blockIdx.x * 128;

    #pragma unroll
    for (int i = tid; i < 128 * V8; i += 256) {
        int r = i / V8, c = i % V8;
        reinterpret_cast<uint4*>(Ahs + r * LD)[c] =
            *reinterpret_cast<const uint4*>(Ah + (size_t)(m0 + r) * K + c * 8);
        reinterpret_cast<uint4*>(Als + r * LD)[c] =
            *reinterpret_cast<const uint4*>(Al + (size_t)(m0 + r) * K + c * 8);
    }

    const int warp = tid >> 5;
    const int wm = warp >> 1, wn = warp & 1;

    #pragma unroll
    for (int pass = 0; pass < 2; pass++) {
        const int n0 = nb + pass * 64;
        #pragma unroll
        for (int i = tid; i < 64 * V8; i += 256) {
            int r = i / V8, c = i % V8;
            reinterpret_cast<uint4*>(Whs + r * LD)[c] =
                *reinterpret_cast<const uint4*>(Wh + (size_t)(n0 + r) * K + c * 8);
            reinterpret_cast<uint4*>(Wls + r * LD)[c] =
                *reinterpret_cast<const uint4*>(Wl + (size_t)(n0 + r) * K + c * 8);
        }
        __syncthreads();

        wmma::fragment<wmma::accumulator, 16, 16, 16, float> c[2][2];
        #pragma unroll
        for (int i = 0; i < 2; i++)
            #pragma unroll
            for (int j = 0; j < 2; j++) wmma::fill_fragment(c[i][j], 0.0f);

        #pragma unroll
        for (int k = 0; k < K; k += 16) {
            wmma::fragment<wmma::matrix_a, 16, 16, 16, __nv_bfloat16, wmma::row_major> fah[2], fal[2];
            wmma::fragment<wmma::matrix_b, 16, 16, 16, __nv_bfloat16, wmma::col_major> fbh[2], fbl[2];
            #pragma unroll
            for (int i = 0; i < 2; i++) {
                wmma::load_matrix_sync(fah[i], Ahs + (wm * 32 + 16 * i) * LD + k, LD);
                wmma::load_matrix_sync(fal[i], Als + (wm * 32 + 16 * i) * LD + k, LD);
                wmma::load_matrix_sync(fbh[i], Whs + (wn * 32 + 16 * i) * LD + k, LD);
                wmma::load_matrix_sync(fbl[i], Wls + (wn * 32 + 16 * i) * LD + k, LD);
            }
            #pragma unroll
            for (int i = 0; i < 2; i++)
                #pragma unroll
                for (int j = 0; j < 2; j++) {
                    wmma::mma_sync(c[i][j], fal[i], fbh[j], c[i][j]);
                    wmma::mma_sync(c[i][j], fah[i], fbl[j], c[i][j]);
                    wmma::mma_sync(c[i][j], fah[i], fbh[j], c[i][j]);
                }
        }
        #pragma unroll
        for (int i = 0; i < 2; i++)
            #pragma unroll
            for (int j = 0; j < 2; j++)
                wmma::store_matrix_sync(C + (size_t)(m0 + wm * 32 + 16 * i) * G_DIM + (n0 + wn * 32 + 16 * j),
                                        c[i][j], G_DIM, wmma::mem_row_major);
        __syncthreads();
    }
}

// =============================================================================
// LSTM recurrence v5: 512 threads, k-quarter split.
// Warp w, lane l: quarter q = l>>3, cell m = w*8 + (l&7).
// Thread computes partials for ALL 4 gates of cell m over k in [q*32,(q+1)*32).
// Weights: k-local 0..19 in RF (10 ull per gate, 40 ull total = 80 regs);
//          k-local 20..31 in smem ws2[c][g][q][m] (ulonglong2, 98,304 B).
// Quarter q adds xp row (q*128+m) to its gate-q partial; 2 shfl_xor rounds
// (8, 16) give every lane the full 4 gate sums; all lanes keep identical c
// (redundant, deterministic); only q==0 writes h / y.
// h double-buffered, t-loop unrolled x2, ONE __syncthreads per step.
// =============================================================================
#define REC_SMEM (98304 + 2 * 128 * 4)

__global__ void __launch_bounds__(512, 1) lstm_rec(const float* __restrict__ xp,
                                                   const float* __restrict__ whh,
                                                   float* __restrict__ y,
                                                   float* __restrict__ hn,
                                                   float* __restrict__ cn)
{
    extern __shared__ __align__(16) char smraw[];
    ulonglong2* ws2  = reinterpret_cast<ulonglong2*>(smraw);      // [3][4][4][128]
    float*      hbuf = reinterpret_cast<float*>(smraw + 98304);   // [2][128]

    const int b    = blockIdx.x;
    const int tid  = threadIdx.x;
    const int lane = tid & 31;
    const int w    = tid >> 5;
    const int q    = lane >> 3;            // k-quarter 0..3
    const int m    = w * 8 + (lane & 7);   // cell 0..127
    const int ko   = q * 32;               // k base

    // ---- load weights: 4 gate rows of cell m, this k-quarter ----
    ull wreg[4][10];                       // k-local 0..19
    #pragma unroll
    for (int g = 0; g < 4; g++) {
        const float* wrow = whh + (size_t)(g * 128 + m) * H_DIM + ko;
        const ull* wp = reinterpret_cast<const ull*>(wrow);
        #pragma unroll
        for (int u = 0; u < 10; u++) wreg[g][u] = wp[u];
        const ulonglong2* wp2 = reinterpret_cast<const ulonglong2*>(wrow + 20);
        #pragma unroll
        for (int c = 0; c < 3; c++)
            ws2[((c * 4 + g) * 4 + q) * 128 + m] = wp2[c];
    }
    if (tid < H_DIM) hbuf[tid] = 0.0f;
    float cst = 0.0f, hlast = 0.0f;
    __syncthreads();

    // xp row for gate q of cell m
    const float* xq = xp + (size_t)b * G_DIM + (q * 128 + m);
    float xv = xq[0];

#define LSTM_STEP(T, RDOFF, WROFF)                                              \
    {                                                                           \
        const ulonglong2* h2 = reinterpret_cast<const ulonglong2*>(hbuf + (RDOFF)) + q * 8; \
        float xn = 0.0f;                                                        \
        if ((T) + 1 < T_DIM)                                                    \
            xn = xq[(size_t)((T) + 1) * B_DIM * G_DIM];                         \
        ull a0 = 0, a1 = 0, a2 = 0, a3 = 0;                                     \
        _Pragma("unroll")                                                       \
        for (int c = 0; c < 5; c++) {                                           \
            ulonglong2 hv = h2[c];                                              \
            a0 = fma2(wreg[0][2 * c], hv.x, a0); a0 = fma2(wreg[0][2 * c + 1], hv.y, a0); \
            a1 = fma2(wreg[1][2 * c], hv.x, a1); a1 = fma2(wreg[1][2 * c + 1], hv.y, a1); \
            a2 = fma2(wreg[2][2 * c], hv.x, a2); a2 = fma2(wreg[2][2 * c + 1], hv.y, a2); \
            a3 = fma2(wreg[3][2 * c], hv.x, a3); a3 = fma2(wreg[3][2 * c + 1], hv.y, a3); \
        }                                                                       \
        _Pragma("unroll")                                                       \
        for (int c = 0; c < 3; c++) {                                           \
            ulonglong2 hv = h2[5 + c];                                          \
            ulonglong2 w0 = ws2[((c * 4 + 0) * 4 + q) * 128 + m];               \
            ulonglong2 w1 = ws2[((c * 4 + 1) * 4 + q) * 128 + m];               \
            ulonglong2 w2 = ws2[((c * 4 + 2) * 4 + q) * 128 + m];               \
            ulonglong2 w3 = ws2[((c * 4 + 3) * 4 + q) * 128 + m];               \
            a0 = fma2(w0.x, hv.x, a0); a0 = fma2(w0.y, hv.y, a0);               \
            a1 = fma2(w1.x, hv.x, a1); a1 = fma2(w1.y, hv.y, a1);               \
            a2 = fma2(w2.x, hv.x, a2); a2 = fma2(w2.y, hv.y, a2);               \
            a3 = fma2(w3.x, hv.x, a3); a3 = fma2(w3.y, hv.y, a3);               \
        }                                                                       \
        float p0 = lo32(a0) + hi32(a0);                                         \
        float p1 = lo32(a1) + hi32(a1);                                         \
        float p2 = lo32(a2) + hi32(a2);                                         \
        float p3 = lo32(a3) + hi32(a3);                                         \
        if (q == 0) p0 += xv; else if (q == 1) p1 += xv;                        \
        else if (q == 2) p2 += xv; else p3 += xv;                               \
        p0 += __shfl_xor_sync(0xffffffffu, p0, 8);                              \
        p1 += __shfl_xor_sync(0xffffffffu, p1, 8);                              \
        p2 += __shfl_xor_sync(0xffffffffu, p2, 8);                              \
        p3 += __shfl_xor_sync(0xffffffffu, p3, 8);                              \
        p0 += __shfl_xor_sync(0xffffffffu, p0, 16);                             \
        p1 += __shfl_xor_sync(0xffffffffu, p1, 16);                             \
        p2 += __shfl_xor_sync(0xffffffffu, p2, 16);                             \
        p3 += __shfl_xor_sync(0xffffffffu, p3, 16);                             \
        float ig = sigmoid_f(p0);                                               \
        float fg = sigmoid_f(p1);                                               \
        float ga = tanh_f(p2);                                                  \
        float og = sigmoid_f(p3);                                               \
        cst = fg * cst + ig * ga;                                               \
        float h = og * tanh_f(cst);                                             \
        hlast = h;                                                              \
        if (q == 0) {                                                           \
            hbuf[(WROFF) + m] = h;                                              \
            y[((size_t)(T) * B_DIM + b) * H_DIM + m] = h;                       \
        }                                                                       \
        __syncthreads();                                                        \
        xv = xn;                                                                \
    }

    for (int t = 0; t < T_DIM; t += 2) {
        LSTM_STEP(t,     0,   128);
        LSTM_STEP(t + 1, 128, 0);
    }
#undef LSTM_STEP

    if (q == 0) {
        hn[b * H_DIM + m] = hlast;
        cn[b * H_DIM + m] = cst;
    }
}

// ---------------- FC head ----------------------------------------------------
__global__ void __launch_bounds__(256) fc_head(const float* __restrict__ A,
                                               const float* __restrict__ W,
                                               const float* __restrict__ bias,
                                               float* __restrict__ C)
{
    __shared__ float ys[32][128];
    __shared__ float wst[128][32];
    const int tid = threadIdx.x;
    const int m0 = blockIdx.x * 32;

    for (int i = tid; i < OUT_DIM * H_DIM; i += 256) {
        int o = i / H_DIM, k = i % H_DIM;
        wst[k][o] = W[i];
    }
    for (int i = tid; i < 32 * H_DIM; i += 256) {
        int r = i / H_DIM, k = i % H_DIM;
        ys[r][k] = A[(size_t)(m0 + r) * H_DIM + k];
    }
    __syncthreads();

    const int o = tid & 31, mq = tid >> 5;
    float a0 = 0.f, a1 = 0.f, a2 = 0.f, a3 = 0.f;
    #pragma unroll 8
    for (int k = 0; k < H_DIM; k++) {
        float w = wst[k][o];
        a0 += ys[mq * 4 + 0][k] * w;
        a1 += ys[mq * 4 + 1][k] * w;
        a2 += ys[mq * 4 + 2][k] * w;
        a3 += ys[mq * 4 + 3][k] * w;
    }
    float bb = bias[o];
    C[(size_t)(m0 + mq * 4 + 0) * OUT_DIM + o] = a0 + bb;
    C[(size_t)(m0 + mq * 4 + 1) * OUT_DIM + o] = a1 + bb;
    C[(size_t)(m0 + mq * 4 + 2) * OUT_DIM + o] = a2 + bb;
    C[(size_t)(m0 + mq * 4 + 3) * OUT_DIM + o] = a3 + bb;
}

extern "C" void kernel_launch(void* const* d_in, const int* in_sizes, int n_in,
                              void* d_out, int out_size)
{
    const float* x     = (const float*)d_in[0];
    const float* w_ih0 = (const float*)d_in[1];
    const float* w_hh0 = (const float*)d_in[2];
    const float* w_ih1 = (const float*)d_in[3];
    const float* w_hh1 = (const float*)d_in[4];
    const float* fc_w  = (const float*)d_in[5];
    const float* fc_b  = (const float*)d_in[6];
    float* out = (float*)d_out;

    float* xp; cudaGetSymbolAddress((void**)&xp, g_xp);
    float* y;  cudaGetSymbolAddress((void**)&y,  g_y);
    __nv_bfloat16 *ah, *al, *wh, *wl;
    cudaGetSymbolAddress((void**)&ah, g_ah);
    cudaGetSymbolAddress((void**)&al, g_al);
    cudaGetSymbolAddress((void**)&wh, g_wh);
    cudaGetSymbolAddress((void**)&wl, g_wl);

    float* hn = out + (size_t)M_TOT * OUT_DIM;
    float* cn = hn + 2 * B_DIM * H_DIM;

    constexpr int SMEM64  = (128 + 64) * (64 + 8) * 2 * 2;    // 55,296 B
    constexpr int SMEM128 = (128 + 64) * (128 + 8) * 2 * 2;   // 104,448 B

    static bool attr_done = false;
    if (!attr_done) {
        cudaFuncSetAttribute(lstm_rec, cudaFuncAttributeMaxDynamicSharedMemorySize, REC_SMEM);
        cudaFuncSetAttribute(gemm_bf<IN_DIM>, cudaFuncAttributeMaxDynamicSharedMemorySize, SMEM64);
        cudaFuncSetAttribute(gemm_bf<H_DIM>,  cudaFuncAttributeMaxDynamicSharedMemorySize, SMEM128);
        attr_done = true;
    }

    dim3 gg(G_DIM / 128, M_TOT / 128);   // 4 x 2048 (2 n-passes per CTA)

    // ---- layer 0 (K = 64) ----
    {
        int n4a = M_TOT * IN_DIM / 4;
        conv_hl<<<(n4a + 255) / 256, 256>>>(x, ah, al, n4a);
        int n4w = G_DIM * IN_DIM / 4;
        conv_hl<<<(n4w + 255) / 256, 256>>>(w_ih0, wh, wl, n4w);
        gemm_bf<IN_DIM><<<gg, 256, SMEM64>>>(ah, al, wh, wl, xp);
        lstm_rec<<<B_DIM, 512, REC_SMEM>>>(xp, w_hh0, y, hn, cn);
    }
    // ---- layer 1 (K = 128) ----
    {
        int n4a = M_TOT * H_DIM / 4;
        conv_hl<<<(n4a + 255) / 256, 256>>>(y, ah, al, n4a);
        int n4w = G_DIM * H_DIM / 4;
        conv_hl<<<(n4w + 255) / 256, 256>>>(w_ih1, wh, wl, n4w);
        gemm_bf<H_DIM><<<gg, 256, SMEM128>>>(ah, al, wh, wl, xp);
        lstm_rec<<<B_DIM, 512, REC_SMEM>>>(xp, w_hh1, y, hn + B_DIM * H_DIM, cn + B_DIM * H_DIM);
    }
    // ---- FC head ----
    fc_head<<<M_TOT / 32, 256>>>(y, fc_w, fc_b, out);
}

// round 14
// speedup vs baseline: 1.2435x; 1.2435x over previous
#include <cuda_runtime.h>
#include <cuda_bf16.h>
#include <mma.h>
#include <cstdint>

using namespace nvcuda;

#define T_DIM   2048
#define B_DIM   128
#define IN_DIM  64
#define H_DIM   128
#define G_DIM   512
#define OUT_DIM 32
#define M_TOT   (T_DIM * B_DIM)   // 262144

typedef unsigned long long ull;

// scratch (device globals: allocation-free per harness rules)
__device__ __align__(16) float g_xp[(size_t)M_TOT * G_DIM];
__device__ __align__(16) float g_y [(size_t)M_TOT * H_DIM];
__device__ __align__(16) __nv_bfloat16 g_wh[G_DIM * H_DIM];
__device__ __align__(16) __nv_bfloat16 g_wl[G_DIM * H_DIM];

// ---------------- activations ------------------------------------------------
__device__ __forceinline__ float tanh_f(float x) {
    float y; asm("tanh.approx.f32 %0, %1;" : "=f"(y) : "f"(x)); return y;
}
__device__ __forceinline__ float sigmoid_f(float x) {
    return 0.5f * tanh_f(0.5f * x) + 0.5f;
}
__device__ __forceinline__ ull fma2(ull a, ull b, ull c) {
    ull d; asm("fma.rn.f32x2 %0, %1, %2, %3;" : "=l"(d) : "l"(a), "l"(b), "l"(c));
    return d;
}
__device__ __forceinline__ float lo32(ull v) { return __uint_as_float((unsigned)(v & 0xffffffffu)); }
__device__ __forceinline__ float hi32(ull v) { return __uint_as_float((unsigned)(v >> 32)); }

// ---------------- fp32 -> bf16 hi/lo split (weights only now) -----------------
__global__ void __launch_bounds__(256) conv_hl(const float* __restrict__ src,
                                               __nv_bfloat16* __restrict__ dh,
                                               __nv_bfloat16* __restrict__ dl,
                                               int n4)
{
    int i = blockIdx.x * 256 + threadIdx.x;
    if (i >= n4) return;
    float4 v = reinterpret_cast<const float4*>(src)[i];
    __nv_bfloat162 h0, h1, l0, l1;
    h0.x = __float2bfloat16_rn(v.x); h0.y = __float2bfloat16_rn(v.y);
    h1.x = __float2bfloat16_rn(v.z); h1.y = __float2bfloat16_rn(v.w);
    l0.x = __float2bfloat16_rn(v.x - __bfloat162float(h0.x));
    l0.y = __float2bfloat16_rn(v.y - __bfloat162float(h0.y));
    l1.x = __float2bfloat16_rn(v.z - __bfloat162float(h1.x));
    l1.y = __float2bfloat16_rn(v.w - __bfloat162float(h1.y));
    union { __nv_bfloat162 b[2]; uint2 u2; } ph, pl;
    ph.b[0] = h0; ph.b[1] = h1; pl.b[0] = l0; pl.b[1] = l1;
    reinterpret_cast<uint2*>(dh)[i] = ph.u2;
    reinterpret_cast<uint2*>(dl)[i] = pl.u2;
}

// ---------------- bf16(hi+lo) GEMM, fused A conversion, full n-reuse ---------
// C[m][g] = sum_k A[m][k]*W[g][k]; 3 terms ah*bh + al*bh + ah*bl.
// Grid = 2048 CTAs; CTA owns 128 m-rows, stages+converts its fp32 A tile ONCE,
// then does 8 sequential 64-wide n-passes (W bf16 from L2).
template<int K>
__global__ void __launch_bounds__(256) gemm_f(const float* __restrict__ A,
                                              const __nv_bfloat16* __restrict__ Wh,
                                              const __nv_bfloat16* __restrict__ Wl,
                                              float* __restrict__ C)
{
    constexpr int LD  = K + 8;
    constexpr int F4R = K / 4;               // float4 per A row
    constexpr int V8  = K / 8;               // uint4 (8 bf16) per W row
    extern __shared__ __nv_bfloat16 sb[];
    __nv_bfloat16* Ahs = sb;                 // [128][LD]
    __nv_bfloat16* Als = Ahs + 128 * LD;
    __nv_bfloat16* Whs = Als + 128 * LD;     // [64][LD]
    __nv_bfloat16* Wls = Whs + 64 * LD;

    const int tid = threadIdx.x;
    const int m0 = blockIdx.x * 128;

    // ---- stage + convert A once (fp32 -> bf16 hi/lo) ----
    #pragma unroll
    for (int i = tid; i < 128 * F4R; i += 256) {
        int r = i / F4R, cq = i % F4R;
        float4 v = *reinterpret_cast<const float4*>(A + (size_t)(m0 + r) * K + cq * 4);
        __nv_bfloat162 h0, h1, l0, l1;
        h0.x = __float2bfloat16_rn(v.x); h0.y = __float2bfloat16_rn(v.y);
        h1.x = __float2bfloat16_rn(v.z); h1.y = __float2bfloat16_rn(v.w);
        l0.x = __float2bfloat16_rn(v.x - __bfloat162float(h0.x));
        l0.y = __float2bfloat16_rn(v.y - __bfloat162float(h0.y));
        l1.x = __float2bfloat16_rn(v.z - __bfloat162float(h1.x));
        l1.y = __float2bfloat16_rn(v.w - __bfloat162float(h1.y));
        union { __nv_bfloat162 b[2]; uint2 u2; } ph, pl;
        ph.b[0] = h0; ph.b[1] = h1; pl.b[0] = l0; pl.b[1] = l1;
        *reinterpret_cast<uint2*>(Ahs + r * LD + cq * 4) = ph.u2;
        *reinterpret_cast<uint2*>(Als + r * LD + cq * 4) = pl.u2;
    }

    const int warp = tid >> 5;
    const int wm = warp >> 1, wn = warp & 1;

    #pragma unroll
    for (int pass = 0; pass < G_DIM / 64; pass++) {
        const int n0 = pass * 64;
        // stage W for this pass (bf16, L2-resident after first CTA)
        #pragma unroll
        for (int i = tid; i < 64 * V8; i += 256) {
            int r = i / V8, c = i % V8;
            reinterpret_cast<uint4*>(Whs + r * LD)[c] =
                *reinterpret_cast<const uint4*>(Wh + (size_t)(n0 + r) * K + c * 8);
            reinterpret_cast<uint4*>(Wls + r * LD)[c] =
                *reinterpret_cast<const uint4*>(Wl + (size_t)(n0 + r) * K + c * 8);
        }
        __syncthreads();

        wmma::fragment<wmma::accumulator, 16, 16, 16, float> c[2][2];
        #pragma unroll
        for (int i = 0; i < 2; i++)
            #pragma unroll
            for (int j = 0; j < 2; j++) wmma::fill_fragment(c[i][j], 0.0f);

        #pragma unroll
        for (int k = 0; k < K; k += 16) {
            wmma::fragment<wmma::matrix_a, 16, 16, 16, __nv_bfloat16, wmma::row_major> fah[2], fal[2];
            wmma::fragment<wmma::matrix_b, 16, 16, 16, __nv_bfloat16, wmma::col_major> fbh[2], fbl[2];
            #pragma unroll
            for (int i = 0; i < 2; i++) {
                wmma::load_matrix_sync(fah[i], Ahs + (wm * 32 + 16 * i) * LD + k, LD);
                wmma::load_matrix_sync(fal[i], Als + (wm * 32 + 16 * i) * LD + k, LD);
                wmma::load_matrix_sync(fbh[i], Whs + (wn * 32 + 16 * i) * LD + k, LD);
                wmma::load_matrix_sync(fbl[i], Wls + (wn * 32 + 16 * i) * LD + k, LD);
            }
            #pragma unroll
            for (int i = 0; i < 2; i++)
                #pragma unroll
                for (int j = 0; j < 2; j++) {
                    wmma::mma_sync(c[i][j], fal[i], fbh[j], c[i][j]);
                    wmma::mma_sync(c[i][j], fah[i], fbl[j], c[i][j]);
                    wmma::mma_sync(c[i][j], fah[i], fbh[j], c[i][j]);
                }
        }
        #pragma unroll
        for (int i = 0; i < 2; i++)
            #pragma unroll
            for (int j = 0; j < 2; j++)
                wmma::store_matrix_sync(C + (size_t)(m0 + wm * 32 + 16 * i) * G_DIM + (n0 + wn * 32 + 16 * j),
                                        c[i][j], G_DIM, wmma::mem_row_major);
        __syncthreads();
    }
}

// =============================================================================
// LSTM recurrence (R8-proven, FROZEN): lane-pair k-split, 1 barrier/step.
// =============================================================================
#define REC_SMEM (65536 + 2 * 128 * 4)

__global__ void __launch_bounds__(256, 1) lstm_rec(const float* __restrict__ xp,
                                                   const float* __restrict__ whh,
                                                   float* __restrict__ y,
                                                   float* __restrict__ hn,
                                                   float* __restrict__ cn)
{
    extern __shared__ __align__(16) char smraw[];
    ulonglong2* ws2  = reinterpret_cast<ulonglong2*>(smraw);      // [4][4][2][128]
    float*      hbuf = reinterpret_cast<float*>(smraw + 65536);   // [2][128]

    const int b    = blockIdx.x;
    const int tid  = threadIdx.x;
    const int lane = tid & 31;
    const int w    = tid >> 5;
    const int half = lane >> 4;
    const int m    = w * 16 + (lane & 15);
    const int ko   = half * 64;

    ull wreg[4][24];
    #pragma unroll
    for (int g = 0; g < 4; g++) {
        const ull* wp = reinterpret_cast<const ull*>(whh + (size_t)(g * 128 + m) * H_DIM + ko);
        #pragma unroll
        for (int u = 0; u < 24; u++) wreg[g][u] = wp[u];
        const ulonglong2* wp2 = reinterpret_cast<const ulonglong2*>(wp + 24);
        #pragma unroll
        for (int c = 0; c < 4; c++)
            ws2[((c * 4 + g) * 2 + half) * 128 + m] = wp2[c];
    }
    if (tid < H_DIM) hbuf[tid] = 0.0f;
    float cst = 0.0f, hlast = 0.0f;
    __syncthreads();

    const float* xq0 = xp + (size_t)b * G_DIM + (half ? (m + 256) : m);
    const float* xq1 = xp + (size_t)b * G_DIM + (half ? (m + 384) : (m + 128));
    float xv0 = xq0[0], xv1 = xq1[0];

#define LSTM_STEP(T, RDOFF, WROFF)                                              \
    {                                                                           \
        const ulonglong2* h2 = reinterpret_cast<const ulonglong2*>(hbuf + (RDOFF)) + half * 16; \
        float xn0 = 0.0f, xn1 = 0.0f;                                           \
        if ((T) + 1 < T_DIM) {                                                  \
            size_t off = (size_t)((T) + 1) * B_DIM * G_DIM;                     \
            xn0 = xq0[off]; xn1 = xq1[off];                                     \
        }                                                                       \
        ull a0 = 0, a1 = 0, a2 = 0, a3 = 0;                                     \
        _Pragma("unroll")                                                       \
        for (int c = 0; c < 12; c++) {                                          \
            ulonglong2 hv = h2[c];                                              \
            a0 = fma2(wreg[0][2 * c], hv.x, a0); a0 = fma2(wreg[0][2 * c + 1], hv.y, a0); \
            a1 = fma2(wreg[1][2 * c], hv.x, a1); a1 = fma2(wreg[1][2 * c + 1], hv.y, a1); \
            a2 = fma2(wreg[2][2 * c], hv.x, a2); a2 = fma2(wreg[2][2 * c + 1], hv.y, a2); \
            a3 = fma2(wreg[3][2 * c], hv.x, a3); a3 = fma2(wreg[3][2 * c + 1], hv.y, a3); \
        }                                                                       \
        _Pragma("unroll")                                                       \
        for (int c = 0; c < 4; c++) {                                           \
            ulonglong2 hv = h2[12 + c];                                         \
            ulonglong2 w0 = ws2[((c * 4 + 0) * 2 + half) * 128 + m];            \
            ulonglong2 w1 = ws2[((c * 4 + 1) * 2 + half) * 128 + m];            \
            ulonglong2 w2 = ws2[((c * 4 + 2) * 2 + half) * 128 + m];            \
            ulonglong2 w3 = ws2[((c * 4 + 3) * 2 + half) * 128 + m];            \
            a0 = fma2(w0.x, hv.x, a0); a0 = fma2(w0.y, hv.y, a0);               \
            a1 = fma2(w1.x, hv.x, a1); a1 = fma2(w1.y, hv.y, a1);               \
            a2 = fma2(w2.x, hv.x, a2); a2 = fma2(w2.y, hv.y, a2);               \
            a3 = fma2(w3.x, hv.x, a3); a3 = fma2(w3.y, hv.y, a3);               \
        }                                                                       \
        float p0 = lo32(a0) + hi32(a0);                                         \
        float p1 = lo32(a1) + hi32(a1);                                         \
        float p2 = lo32(a2) + hi32(a2);                                         \
        float p3 = lo32(a3) + hi32(a3);                                         \
        if (half) { p2 += xv0; p3 += xv1; } else { p0 += xv0; p1 += xv1; }      \
        float q0 = __shfl_xor_sync(0xffffffffu, p0, 16);                        \
        float q1 = __shfl_xor_sync(0xffffffffu, p1, 16);                        \
        float q2 = __shfl_xor_sync(0xffffffffu, p2, 16);                        \
        float q3 = __shfl_xor_sync(0xffffffffu, p3, 16);                        \
        if (!half) {                                                            \
            float ig = sigmoid_f(p0 + q0);                                      \
            float fg = sigmoid_f(p1 + q1);                                      \
            float ga = tanh_f(p2 + q2);                                         \
            float og = sigmoid_f(p3 + q3);                                      \
            cst = fg * cst + ig * ga;                                           \
            float h = og * tanh_f(cst);                                         \
            hlast = h;                                                          \
            hbuf[(WROFF) + m] = h;                                              \
            y[((size_t)(T) * B_DIM + b) * H_DIM + m] = h;                       \
        }                                                                       \
        __syncthreads();                                                        \
        xv0 = xn0; xv1 = xn1;                                                   \
    }

    for (int t = 0; t < T_DIM; t += 2) {
        LSTM_STEP(t,     0,   128);
        LSTM_STEP(t + 1, 128, 0);
    }
#undef LSTM_STEP

    if (!half) {
        hn[b * H_DIM + m] = hlast;
        cn[b * H_DIM + m] = cst;
    }
}

// ---------------- FC head ----------------------------------------------------
__global__ void __launch_bounds__(256) fc_head(const float* __restrict__ A,
                                               const float* __restrict__ W,
                                               const float* __restrict__ bias,
                                               float* __restrict__ C)
{
    __shared__ float ys[32][128];
    __shared__ float wst[128][32];
    const int tid = threadIdx.x;
    const int m0 = blockIdx.x * 32;

    for (int i = tid; i < OUT_DIM * H_DIM; i += 256) {
        int o = i / H_DIM, k = i % H_DIM;
        wst[k][o] = W[i];
    }
    for (int i = tid; i < 32 * H_DIM; i += 256) {
        int r = i / H_DIM, k = i % H_DIM;
        ys[r][k] = A[(size_t)(m0 + r) * H_DIM + k];
    }
    __syncthreads();

    const int o = tid & 31, mq = tid >> 5;
    float a0 = 0.f, a1 = 0.f, a2 = 0.f, a3 = 0.f;
    #pragma unroll 8
    for (int k = 0; k < H_DIM; k++) {
        float w = wst[k][o];
        a0 += ys[mq * 4 + 0][k] * w;
        a1 += ys[mq * 4 + 1][k] * w;
        a2 += ys[mq * 4 + 2][k] * w;
        a3 += ys[mq * 4 + 3][k] * w;
    }
    float bb = bias[o];
    C[(size_t)(m0 + mq * 4 + 0) * OUT_DIM + o] = a0 + bb;
    C[(size_t)(m0 + mq * 4 + 1) * OUT_DIM + o] = a1 + bb;
    C[(size_t)(m0 + mq * 4 + 2) * OUT_DIM + o] = a2 + bb;
    C[(size_t)(m0 + mq * 4 + 3) * OUT_DIM + o] = a3 + bb;
}

extern "C" void kernel_launch(void* const* d_in, const int* in_sizes, int n_in,
                              void* d_out, int out_size)
{
    const float* x     = (const float*)d_in[0];
    const float* w_ih0 = (const float*)d_in[1];
    const float* w_hh0 = (const float*)d_in[2];
    const float* w_ih1 = (const float*)d_in[3];
    const float* w_hh1 = (const float*)d_in[4];
    const float* fc_w  = (const float*)d_in[5];
    const float* fc_b  = (const float*)d_in[6];
    float* out = (float*)d_out;

    float* xp; cudaGetSymbolAddress((void**)&xp, g_xp);
    float* y;  cudaGetSymbolAddress((void**)&y,  g_y);
    __nv_bfloat16 *wh, *wl;
    cudaGetSymbolAddress((void**)&wh, g_wh);
    cudaGetSymbolAddress((void**)&wl, g_wl);

    float* hn = out + (size_t)M_TOT * OUT_DIM;
    float* cn = hn + 2 * B_DIM * H_DIM;

    constexpr int SMEM64  = (128 + 64) * (64 + 8) * 2 * 2;    // 55,296 B
    constexpr int SMEM128 = (128 + 64) * (128 + 8) * 2 * 2;   // 104,448 B

    static bool attr_done = false;
    if (!attr_done) {
        cudaFuncSetAttribute(lstm_rec, cudaFuncAttributeMaxDynamicSharedMemorySize, REC_SMEM);
        cudaFuncSetAttribute(gemm_f<IN_DIM>, cudaFuncAttributeMaxDynamicSharedMemorySize, SMEM64);
        cudaFuncSetAttribute(gemm_f<H_DIM>,  cudaFuncAttributeMaxDynamicSharedMemorySize, SMEM128);
        attr_done = true;
    }

    // ---- layer 0 (K = 64) ----
    {
        int n4w = G_DIM * IN_DIM / 4;
        conv_hl<<<(n4w + 255) / 256, 256>>>(w_ih0, wh, wl, n4w);
        gemm_f<IN_DIM><<<M_TOT / 128, 256, SMEM64>>>(x, wh, wl, xp);
        lstm_rec<<<B_DIM, 256, REC_SMEM>>>(xp, w_hh0, y, hn, cn);
    }
    // ---- layer 1 (K = 128) ----
    {
        int n4w = G_DIM * H_DIM / 4;
        conv_hl<<<(n4w + 255) / 256, 256>>>(w_ih1, wh, wl, n4w);
        gemm_f<H_DIM><<<M_TOT / 128, 256, SMEM128>>>(y, wh, wl, xp);
        lstm_rec<<<B_DIM, 256, REC_SMEM>>>(xp, w_hh1, y, hn + B_DIM * H_DIM, cn + B_DIM * H_DIM);
    }
    // ---- FC head ----
    fc_head<<<M_TOT / 32, 256>>>(y, fc_w, fc_b, out);
}